// round 1
// baseline (speedup 1.0000x reference)
#include <cuda_runtime.h>
#include <math.h>

#define BDIM 2
#define TLEN 2048
#define CDIM 1024
#define NH   16
#define DH   64
#define MROWS (BDIM * TLEN)   // 4096

// Scratch (allocation-free rule: __device__ globals)
__device__ float g_q[(size_t)BDIM * NH * TLEN * DH];
__device__ float g_k[(size_t)BDIM * NH * TLEN * DH];
__device__ float g_v[(size_t)BDIM * NH * TLEN * DH];
__device__ float g_att[(size_t)MROWS * CDIM];   // [B,T,C] layout

// ----------------------------------------------------------------------------
// GEMM: C[m,n] = sum_k A[m,k] * W[n,k]   (torch Linear: x @ W^T)
// BM=BN=128, BK=16, 256 threads, 8x8 microtile per thread.
// SCATTER=1: blockIdx.z selects (Wq,g_q)/(Wk,g_k)/(Wv,g_v), scatter to [B,H,T,Dh].
// SCATTER=0: A := g_att, W := W0, plain store to Cout.
// ----------------------------------------------------------------------------
template <int SCATTER>
__global__ void __launch_bounds__(256) gemm_nt_kernel(
    const float* __restrict__ A,
    const float* __restrict__ W0,
    const float* __restrict__ W1,
    const float* __restrict__ W2,
    float* __restrict__ Cout)
{
    const int K = CDIM;
    __shared__ float As[128][17];
    __shared__ float Ws[128][17];

    const float* W;
    float* dst;
    if (SCATTER) {
        int z = blockIdx.z;
        W   = (z == 0) ? W0  : (z == 1) ? W1  : W2;
        dst = (z == 0) ? g_q : (z == 1) ? g_k : g_v;
    } else {
        W   = W0;
        dst = Cout;
    }
    const float* Ap = SCATTER ? A : g_att;

    int bm0 = blockIdx.y * 128;
    int bn0 = blockIdx.x * 128;
    int tx  = threadIdx.x & 15;
    int ty  = threadIdx.x >> 4;

    float acc[8][8];
#pragma unroll
    for (int i = 0; i < 8; i++)
#pragma unroll
        for (int j = 0; j < 8; j++) acc[i][j] = 0.f;

    for (int k0 = 0; k0 < K; k0 += 16) {
        // Load 128x16 A-tile and W-tile (512 float4 each, 2 per thread)
#pragma unroll
        for (int l = 0; l < 2; l++) {
            int idx = threadIdx.x + l * 256;      // 0..511
            int r   = idx >> 2;                   // 0..127
            int c4  = (idx & 3) * 4;              // 0,4,8,12
            float4 av = *(const float4*)&Ap[(size_t)(bm0 + r) * K + k0 + c4];
            As[r][c4 + 0] = av.x; As[r][c4 + 1] = av.y;
            As[r][c4 + 2] = av.z; As[r][c4 + 3] = av.w;
            float4 wv = *(const float4*)&W[(size_t)(bn0 + r) * K + k0 + c4];
            Ws[r][c4 + 0] = wv.x; Ws[r][c4 + 1] = wv.y;
            Ws[r][c4 + 2] = wv.z; Ws[r][c4 + 3] = wv.w;
        }
        __syncthreads();

#pragma unroll
        for (int kk = 0; kk < 16; kk++) {
            float a[8], b[8];
#pragma unroll
            for (int i = 0; i < 8; i++) a[i] = As[i * 16 + ty][kk];
#pragma unroll
            for (int j = 0; j < 8; j++) b[j] = Ws[j * 16 + tx][kk];
#pragma unroll
            for (int i = 0; i < 8; i++)
#pragma unroll
                for (int j = 0; j < 8; j++) acc[i][j] += a[i] * b[j];
        }
        __syncthreads();
    }

#pragma unroll
    for (int i = 0; i < 8; i++) {
#pragma unroll
        for (int j = 0; j < 8; j++) {
            int m = bm0 + i * 16 + ty;
            int n = bn0 + j * 16 + tx;
            if (SCATTER) {
                int bb = m >> 11;        // / 2048
                int tt = m & 2047;
                int hh = n >> 6;         // / 64
                int dd = n & 63;
                dst[(((size_t)bb * NH + hh) * TLEN + tt) * DH + dd] = acc[i][j];
            } else {
                dst[(size_t)m * CDIM + n] = acc[i][j];
            }
        }
    }
}

// ----------------------------------------------------------------------------
// Causal flash attention.
// grid = (T/64, B*H). 256 threads = 64 q-rows x 4 d-groups.
// q row in registers; K/V/P tiles in dynamic smem (LD=68 pad, conflict-free).
// Key index mapping j = jj*4 + dg keeps the 4 d-groups on distinct banks.
// ----------------------------------------------------------------------------
#define ALD 68
__global__ void __launch_bounds__(256) attn_kernel()
{
    extern __shared__ float sm[];
    float* ps = sm;                 // 64*ALD (q staging, then P tile)
    float* ks = sm + 64 * ALD;      // 64*ALD
    float* vs = sm + 2 * 64 * ALD;  // 64*ALD

    int qt = blockIdx.x;            // 0..31
    int bh = blockIdx.y;            // 0..31 = b*NH + h
    const float* qg = g_q + (size_t)bh * TLEN * DH;
    const float* kg = g_k + (size_t)bh * TLEN * DH;
    const float* vg = g_v + (size_t)bh * TLEN * DH;

    int tid = threadIdx.x;
    int row = tid >> 2;             // 0..63
    int dg  = tid & 3;              // 0..3
    int qidx = qt * 64 + row;

    // stage q tile -> smem -> registers
#pragma unroll
    for (int l = 0; l < 4; l++) {
        int idx = tid + l * 256;            // 0..1023 float4s
        int r   = idx >> 4;
        int c4  = (idx & 15) * 4;
        *(float4*)&ps[r * ALD + c4] =
            *(const float4*)&qg[(size_t)(qt * 64 + r) * DH + c4];
    }
    __syncthreads();
    float qreg[64];
#pragma unroll
    for (int d = 0; d < 64; d++) qreg[d] = ps[row * ALD + d];
    __syncthreads();

    float m = -INFINITY, lsum_tot = 0.f;
    float acc[16];
#pragma unroll
    for (int i = 0; i < 16; i++) acc[i] = 0.f;

    for (int kt = 0; kt <= qt; kt++) {
        // load K and V 64x64 tiles
#pragma unroll
        for (int lo = 0; lo < 4; lo++) {
            int idx = tid + lo * 256;
            int r   = idx >> 4;
            int c4  = (idx & 15) * 4;
            *(float4*)&ks[r * ALD + c4] =
                *(const float4*)&kg[(size_t)(kt * 64 + r) * DH + c4];
            *(float4*)&vs[r * ALD + c4] =
                *(const float4*)&vg[(size_t)(kt * 64 + r) * DH + c4];
        }
        __syncthreads();

        // scores for this thread's 16 keys (j = jj*4 + dg)
        float tmax = -INFINITY;
#pragma unroll 2
        for (int jj = 0; jj < 16; jj++) {
            const float* kr = &ks[(jj * 4 + dg) * ALD];
            float sum = 0.f;
#pragma unroll
            for (int d = 0; d < 64; d++) sum += qreg[d] * kr[d];
            sum *= 0.125f;  // 1/sqrt(64)
            if (kt == qt && (kt * 64 + jj * 4 + dg) > qidx) sum = -INFINITY;
            ps[row * ALD + jj * 4 + dg] = sum;
            tmax = fmaxf(tmax, sum);
        }
        // row-max across the 4 d-group threads (consecutive lanes)
        tmax = fmaxf(tmax, __shfl_xor_sync(0xffffffffu, tmax, 1));
        tmax = fmaxf(tmax, __shfl_xor_sync(0xffffffffu, tmax, 2));
        float mnew  = fmaxf(m, tmax);
        float scale = __expf(m - mnew);   // m=-inf first tile -> 0

        float lsum = 0.f;
#pragma unroll 4
        for (int jj = 0; jj < 16; jj++) {
            float p = __expf(ps[row * ALD + jj * 4 + dg] - mnew);
            ps[row * ALD + jj * 4 + dg] = p;
            lsum += p;
        }
        lsum += __shfl_xor_sync(0xffffffffu, lsum, 1);
        lsum += __shfl_xor_sync(0xffffffffu, lsum, 2);
        lsum_tot = lsum_tot * scale + lsum;
        m = mnew;
#pragma unroll
        for (int i = 0; i < 16; i++) acc[i] *= scale;
        __syncthreads();   // all P for the row visible

        // acc[d] += sum_j P[row][j] * V[j][d], this thread owns d = dg*16..+15
#pragma unroll 4
        for (int j = 0; j < 64; j++) {
            float p = ps[row * ALD + j];
            const float* vr = &vs[j * ALD + dg * 16];
#pragma unroll
            for (int i = 0; i < 16; i++) acc[i] += p * vr[i];
        }
        __syncthreads();   // protect ks/vs/ps for next tile
    }

    // write to g_att in [B,T,C] layout
    int b = bh / NH, h = bh % NH;
    float inv = 1.f / lsum_tot;
    float* op = g_att + ((size_t)b * TLEN + qt * 64 + row) * CDIM + h * DH + dg * 16;
#pragma unroll
    for (int i = 0; i < 16; i++) op[i] = acc[i] * inv;
}

// ----------------------------------------------------------------------------
extern "C" void kernel_launch(void* const* d_in, const int* in_sizes, int n_in,
                              void* d_out, int out_size)
{
    const float* x  = (const float*)d_in[0];
    const float* Wq = (const float*)d_in[1];
    const float* Wk = (const float*)d_in[2];
    const float* Wv = (const float*)d_in[3];
    const float* Wo = (const float*)d_in[4];
    float* out = (float*)d_out;

    // 1) fused QKV projections -> g_q/g_k/g_v in [B,H,T,Dh]
    gemm_nt_kernel<1><<<dim3(CDIM / 128, MROWS / 128, 3), 256>>>(
        x, Wq, Wk, Wv, nullptr);

    // 2) causal flash attention -> g_att in [B,T,C]
    const int smem = 3 * 64 * ALD * sizeof(float);   // 52224 B
    cudaFuncSetAttribute(attn_kernel,
                         cudaFuncAttributeMaxDynamicSharedMemorySize, smem);
    attn_kernel<<<dim3(TLEN / 64, BDIM * NH), 256, smem>>>();

    // 3) output projection -> d_out
    gemm_nt_kernel<0><<<dim3(CDIM / 128, MROWS / 128, 1), 256>>>(
        nullptr, Wo, nullptr, nullptr, out);
}

// round 2
// speedup vs baseline: 1.8671x; 1.8671x over previous
#include <cuda_runtime.h>
#include <math.h>

#define BDIM 2
#define TLEN 2048
#define CDIM 1024
#define NH   16
#define DH   64
#define MROWS (BDIM * TLEN)   // 4096

// Scratch (allocation-free rule: __device__ globals)
__device__ float g_q[(size_t)BDIM * NH * TLEN * DH];
__device__ float g_k[(size_t)BDIM * NH * TLEN * DH];
__device__ float g_v[(size_t)BDIM * NH * TLEN * DH];
__device__ float g_att[(size_t)MROWS * CDIM];   // [B,T,C] layout

// ----------------------------------------------------------------------------
// GEMM: C[m,n] = sum_k A[m,k] * W[n,k]   (torch Linear: x @ W^T)
// BM=BN=128, BK=16, 256 threads, 8x8 microtile, double-buffered smem,
// transposed tiles [k][m] so microtile loads are LDS.128.
// ----------------------------------------------------------------------------
#define GLD 132
template <int SCATTER>
__global__ void __launch_bounds__(256, 2) gemm_nt_kernel(
    const float* __restrict__ A,
    const float* __restrict__ W0,
    const float* __restrict__ W1,
    const float* __restrict__ W2,
    float* __restrict__ Cout)
{
    const int K = CDIM;
    __shared__ float As[2][16][GLD];
    __shared__ float Ws[2][16][GLD];

    const float* W;
    float* dst;
    if (SCATTER) {
        int z = blockIdx.z;
        W   = (z == 0) ? W0  : (z == 1) ? W1  : W2;
        dst = (z == 0) ? g_q : (z == 1) ? g_k : g_v;
    } else {
        W   = W0;
        dst = Cout;
    }
    const float* Ap = SCATTER ? A : g_att;

    const int bm0 = blockIdx.y * 128;
    const int bn0 = blockIdx.x * 128;
    const int tx  = threadIdx.x & 15;
    const int ty  = threadIdx.x >> 4;

    // per-thread global load coords (2 float4 per matrix per tile)
    int r0  = threadIdx.x >> 2;                 // 0..63
    int c40 = (threadIdx.x & 3) * 4;            // 0,4,8,12
    int r1  = r0 + 64;

    float acc[8][8];
#pragma unroll
    for (int i = 0; i < 8; i++)
#pragma unroll
        for (int j = 0; j < 8; j++) acc[i][j] = 0.f;

    float4 pa0, pa1, pw0, pw1;
    // prefetch tile 0
    pa0 = *(const float4*)&Ap[(size_t)(bm0 + r0) * K + c40];
    pa1 = *(const float4*)&Ap[(size_t)(bm0 + r1) * K + c40];
    pw0 = *(const float4*)&W [(size_t)(bn0 + r0) * K + c40];
    pw1 = *(const float4*)&W [(size_t)(bn0 + r1) * K + c40];
    // store transposed into buf 0
    As[0][c40 + 0][r0] = pa0.x; As[0][c40 + 1][r0] = pa0.y;
    As[0][c40 + 2][r0] = pa0.z; As[0][c40 + 3][r0] = pa0.w;
    As[0][c40 + 0][r1] = pa1.x; As[0][c40 + 1][r1] = pa1.y;
    As[0][c40 + 2][r1] = pa1.z; As[0][c40 + 3][r1] = pa1.w;
    Ws[0][c40 + 0][r0] = pw0.x; Ws[0][c40 + 1][r0] = pw0.y;
    Ws[0][c40 + 2][r0] = pw0.z; Ws[0][c40 + 3][r0] = pw0.w;
    Ws[0][c40 + 0][r1] = pw1.x; Ws[0][c40 + 1][r1] = pw1.y;
    Ws[0][c40 + 2][r1] = pw1.z; Ws[0][c40 + 3][r1] = pw1.w;
    __syncthreads();

    int buf = 0;
    for (int k0 = 16; k0 <= K; k0 += 16) {
        bool more = (k0 < K);
        if (more) {
            pa0 = *(const float4*)&Ap[(size_t)(bm0 + r0) * K + k0 + c40];
            pa1 = *(const float4*)&Ap[(size_t)(bm0 + r1) * K + k0 + c40];
            pw0 = *(const float4*)&W [(size_t)(bn0 + r0) * K + k0 + c40];
            pw1 = *(const float4*)&W [(size_t)(bn0 + r1) * K + k0 + c40];
        }
#pragma unroll
        for (int kk = 0; kk < 16; kk++) {
            float a[8], b[8];
            *(float4*)&a[0] = *(const float4*)&As[buf][kk][ty * 8];
            *(float4*)&a[4] = *(const float4*)&As[buf][kk][ty * 8 + 4];
            *(float4*)&b[0] = *(const float4*)&Ws[buf][kk][tx * 8];
            *(float4*)&b[4] = *(const float4*)&Ws[buf][kk][tx * 8 + 4];
#pragma unroll
            for (int i = 0; i < 8; i++)
#pragma unroll
                for (int j = 0; j < 8; j++) acc[i][j] += a[i] * b[j];
        }
        if (more) {
            int nb = buf ^ 1;
            As[nb][c40 + 0][r0] = pa0.x; As[nb][c40 + 1][r0] = pa0.y;
            As[nb][c40 + 2][r0] = pa0.z; As[nb][c40 + 3][r0] = pa0.w;
            As[nb][c40 + 0][r1] = pa1.x; As[nb][c40 + 1][r1] = pa1.y;
            As[nb][c40 + 2][r1] = pa1.z; As[nb][c40 + 3][r1] = pa1.w;
            Ws[nb][c40 + 0][r0] = pw0.x; Ws[nb][c40 + 1][r0] = pw0.y;
            Ws[nb][c40 + 2][r0] = pw0.z; Ws[nb][c40 + 3][r0] = pw0.w;
            Ws[nb][c40 + 0][r1] = pw1.x; Ws[nb][c40 + 1][r1] = pw1.y;
            Ws[nb][c40 + 2][r1] = pw1.z; Ws[nb][c40 + 3][r1] = pw1.w;
            __syncthreads();
            buf = nb;
        }
    }

    // Epilogue: thread owns rows bm0+ty*8..+7, cols bn0+tx*8..+7 (contiguous)
#pragma unroll
    for (int i = 0; i < 8; i++) {
        int m = bm0 + ty * 8 + i;
#pragma unroll
        for (int jv = 0; jv < 2; jv++) {
            int n = bn0 + tx * 8 + jv * 4;
            float4 val = make_float4(acc[i][jv * 4 + 0], acc[i][jv * 4 + 1],
                                     acc[i][jv * 4 + 2], acc[i][jv * 4 + 3]);
            if (SCATTER) {
                int bb = m >> 11;
                int tt = m & 2047;
                int hh = n >> 6;
                int dd = n & 63;
                *(float4*)&dst[(((size_t)bb * NH + hh) * TLEN + tt) * DH + dd] = val;
            } else {
                *(float4*)&dst[(size_t)m * CDIM + n] = val;
            }
        }
    }
}

// ----------------------------------------------------------------------------
// Causal flash attention, register-tiled.
// grid = (T/64, B*H). 256 threads = 16 row-groups (ry) x 16 col-groups (cx).
// Thread owns 4x4 of S and 4x4 of O. Row softmax stats via shfl within the
// 16-lane group (half-warp shares ry). Smem LD=65 -> broadcast/2-way reads.
// ----------------------------------------------------------------------------
#define ALD 65
__global__ void __launch_bounds__(256, 3) attn_kernel()
{
    extern __shared__ float sm[];
    float* qs = sm;                  // [64][ALD]
    float* ks = sm + 64 * ALD;
    float* vs = sm + 2 * 64 * ALD;
    float* ps = sm + 3 * 64 * ALD;

    const int qt = blockIdx.x;       // 0..31
    const int bh = blockIdx.y;       // 0..31
    const float* qg = g_q + (size_t)bh * TLEN * DH;
    const float* kg = g_k + (size_t)bh * TLEN * DH;
    const float* vg = g_v + (size_t)bh * TLEN * DH;

    const int tid = threadIdx.x;
    const int ry  = tid >> 4;        // 0..15
    const int cx  = tid & 15;        // 0..15

    // stage q tile (pre-scaled by 1/sqrt(Dh))
#pragma unroll
    for (int l = 0; l < 4; l++) {
        int idx = tid + l * 256;     // 0..1023
        int r   = idx >> 4;
        int c4  = (idx & 15) * 4;
        float4 v = *(const float4*)&qg[(size_t)(qt * 64 + r) * DH + c4];
        qs[r * ALD + c4 + 0] = v.x * 0.125f;
        qs[r * ALD + c4 + 1] = v.y * 0.125f;
        qs[r * ALD + c4 + 2] = v.z * 0.125f;
        qs[r * ALD + c4 + 3] = v.w * 0.125f;
    }

    float m[4], lsum[4], o[4][4];
#pragma unroll
    for (int i = 0; i < 4; i++) { m[i] = -INFINITY; lsum[i] = 0.f; }
#pragma unroll
    for (int i = 0; i < 4; i++)
#pragma unroll
        for (int j = 0; j < 4; j++) o[i][j] = 0.f;

    for (int kt = 0; kt <= qt; kt++) {
        // load K,V tiles
#pragma unroll
        for (int l = 0; l < 4; l++) {
            int idx = tid + l * 256;
            int r   = idx >> 4;
            int c4  = (idx & 15) * 4;
            float4 kv = *(const float4*)&kg[(size_t)(kt * 64 + r) * DH + c4];
            ks[r * ALD + c4 + 0] = kv.x; ks[r * ALD + c4 + 1] = kv.y;
            ks[r * ALD + c4 + 2] = kv.z; ks[r * ALD + c4 + 3] = kv.w;
            float4 vv = *(const float4*)&vg[(size_t)(kt * 64 + r) * DH + c4];
            vs[r * ALD + c4 + 0] = vv.x; vs[r * ALD + c4 + 1] = vv.y;
            vs[r * ALD + c4 + 2] = vv.z; vs[r * ALD + c4 + 3] = vv.w;
        }
        __syncthreads();

        // S = q @ k^T (4x4 register tile)
        float s[4][4];
#pragma unroll
        for (int i = 0; i < 4; i++)
#pragma unroll
            for (int j = 0; j < 4; j++) s[i][j] = 0.f;
#pragma unroll 16
        for (int d = 0; d < 64; d++) {
            float a[4], b[4];
#pragma unroll
            for (int i = 0; i < 4; i++) a[i] = qs[(ry * 4 + i) * ALD + d];
#pragma unroll
            for (int j = 0; j < 4; j++) b[j] = ks[(cx * 4 + j) * ALD + d];
#pragma unroll
            for (int i = 0; i < 4; i++)
#pragma unroll
                for (int j = 0; j < 4; j++) s[i][j] += a[i] * b[j];
        }

        // causal mask (diagonal tile only)
        if (kt == qt) {
#pragma unroll
            for (int i = 0; i < 4; i++)
#pragma unroll
                for (int j = 0; j < 4; j++)
                    if (cx * 4 + j > ry * 4 + i) s[i][j] = -INFINITY;
        }

        // row max across 4 cols then across the 16 cx lanes
        float mx[4];
#pragma unroll
        for (int i = 0; i < 4; i++)
            mx[i] = fmaxf(fmaxf(s[i][0], s[i][1]), fmaxf(s[i][2], s[i][3]));
#pragma unroll
        for (int off = 1; off < 16; off <<= 1)
#pragma unroll
            for (int i = 0; i < 4; i++)
                mx[i] = fmaxf(mx[i], __shfl_xor_sync(0xffffffffu, mx[i], off));

        float scale[4];
#pragma unroll
        for (int i = 0; i < 4; i++) {
            float mnew = fmaxf(m[i], mx[i]);
            scale[i] = __expf(m[i] - mnew);
            m[i] = mnew;
        }

        float rs[4] = {0.f, 0.f, 0.f, 0.f};
#pragma unroll
        for (int i = 0; i < 4; i++) {
#pragma unroll
            for (int j = 0; j < 4; j++) {
                float p = __expf(s[i][j] - m[i]);
                ps[(ry * 4 + i) * ALD + cx * 4 + j] = p;
                rs[i] += p;
            }
        }
#pragma unroll
        for (int off = 1; off < 16; off <<= 1)
#pragma unroll
            for (int i = 0; i < 4; i++)
                rs[i] += __shfl_xor_sync(0xffffffffu, rs[i], off);
#pragma unroll
        for (int i = 0; i < 4; i++) {
            lsum[i] = lsum[i] * scale[i] + rs[i];
#pragma unroll
            for (int j = 0; j < 4; j++) o[i][j] *= scale[i];
        }
        __syncthreads();   // ps visible to all

        // O += P @ V (thread cols cx*4..+3)
#pragma unroll 8
        for (int j = 0; j < 64; j++) {
            float a[4], b[4];
#pragma unroll
            for (int i = 0; i < 4; i++) a[i] = ps[(ry * 4 + i) * ALD + j];
#pragma unroll
            for (int jj = 0; jj < 4; jj++) b[jj] = vs[j * ALD + cx * 4 + jj];
#pragma unroll
            for (int i = 0; i < 4; i++)
#pragma unroll
                for (int jj = 0; jj < 4; jj++) o[i][jj] += a[i] * b[jj];
        }
        __syncthreads();   // protect tiles for next iter
    }

    // write to g_att [B,T,C]
    const int b = bh >> 4;
    const int h = bh & 15;
#pragma unroll
    for (int i = 0; i < 4; i++) {
        float inv = 1.f / lsum[i];
        int t = qt * 64 + ry * 4 + i;
        float4 val = make_float4(o[i][0] * inv, o[i][1] * inv,
                                 o[i][2] * inv, o[i][3] * inv);
        *(float4*)&g_att[((size_t)b * TLEN + t) * CDIM + h * DH + cx * 4] = val;
    }
}

// ----------------------------------------------------------------------------
extern "C" void kernel_launch(void* const* d_in, const int* in_sizes, int n_in,
                              void* d_out, int out_size)
{
    const float* x  = (const float*)d_in[0];
    const float* Wq = (const float*)d_in[1];
    const float* Wk = (const float*)d_in[2];
    const float* Wv = (const float*)d_in[3];
    const float* Wo = (const float*)d_in[4];
    float* out = (float*)d_out;

    gemm_nt_kernel<1><<<dim3(CDIM / 128, MROWS / 128, 3), 256>>>(
        x, Wq, Wk, Wv, nullptr);

    const int smem = 4 * 64 * ALD * sizeof(float);   // 66560 B
    cudaFuncSetAttribute(attn_kernel,
                         cudaFuncAttributeMaxDynamicSharedMemorySize, smem);
    attn_kernel<<<dim3(TLEN / 64, BDIM * NH), 256, smem>>>();

    gemm_nt_kernel<0><<<dim3(CDIM / 128, MROWS / 128, 1), 256>>>(
        nullptr, Wo, nullptr, nullptr, out);
}

// round 4
// speedup vs baseline: 2.8567x; 1.5300x over previous
#include <cuda_runtime.h>
#include <cstdint>
#include <math.h>

#define BDIM 2
#define TLEN 2048
#define CDIM 1024
#define NH   16
#define DH   64
#define MROWS (BDIM * TLEN)   // 4096

// Scratch (allocation-free rule: __device__ globals)
__device__ float g_q[(size_t)BDIM * NH * TLEN * DH];
__device__ float g_k[(size_t)BDIM * NH * TLEN * DH];
__device__ float g_v[(size_t)BDIM * NH * TLEN * DH];
__device__ float g_att[(size_t)MROWS * CDIM];   // [B,T,C] layout

// ============================================================================
// helpers
// ============================================================================
__device__ __forceinline__ float f2tf32f(float f) {
    uint32_t r;
    asm("cvt.rna.tf32.f32 %0, %1;" : "=r"(r) : "f"(f));
    return __uint_as_float(r);
}
__device__ __forceinline__ void mma_tf32(float* d, const uint32_t* a,
                                         const uint32_t* b) {
    asm volatile(
        "mma.sync.aligned.m16n8k8.row.col.f32.tf32.tf32.f32 "
        "{%0,%1,%2,%3}, {%4,%5,%6,%7}, {%8,%9}, {%0,%1,%2,%3};"
        : "+f"(d[0]), "+f"(d[1]), "+f"(d[2]), "+f"(d[3])
        : "r"(a[0]), "r"(a[1]), "r"(a[2]), "r"(a[3]), "r"(b[0]), "r"(b[1]));
}

// ============================================================================
// tf32 mma.sync GEMM: C[m,n] = sum_k A[m,k] * W[n,k]   (x @ W^T)
// CTA 128x128, 8 warps (4x2), warp tile 32x64, BK=16 double-buffered.
// SMEM stride 20 floats -> conflict-free tf32 fragment loads.
// SCATTER=1: blockIdx.z selects Wq/Wk/Wv, scatter into [B,H,T,Dh].
// ============================================================================
#define BK  16
#define LDT 20
template <int SCATTER>
__global__ void __launch_bounds__(256, 2) gemm_mma_kernel(
    const float* __restrict__ A,
    const float* __restrict__ W0,
    const float* __restrict__ W1,
    const float* __restrict__ W2,
    float* __restrict__ Cout)
{
    const int K = CDIM;
    __shared__ float As[2][128][LDT];
    __shared__ float Ws[2][128][LDT];

    const float* W;
    float* dst;
    if (SCATTER) {
        int z = blockIdx.z;
        W   = (z == 0) ? W0  : (z == 1) ? W1  : W2;
        dst = (z == 0) ? g_q : (z == 1) ? g_k : g_v;
    } else {
        W   = W0;
        dst = Cout;
    }
    const float* Ap = SCATTER ? A : g_att;

    const int bm0  = blockIdx.y * 128;
    const int bn0  = blockIdx.x * 128;
    const int tid  = threadIdx.x;
    const int lane = tid & 31;
    const int wid  = tid >> 5;
    const int g    = lane >> 2;          // group id 0..7
    const int tig  = lane & 3;           // thread-in-group 0..3
    const int wm   = (wid & 3) * 32;     // warp m offset
    const int wn   = (wid >> 2) * 64;    // warp n offset

    // global load coords: 2 float4 per matrix per tile
    const int r0 = tid >> 2;             // 0..63
    const int c4 = (tid & 3) * 4;        // 0,4,8,12
    const int r1 = r0 + 64;

    float d[2][8][4];
#pragma unroll
    for (int mc = 0; mc < 2; mc++)
#pragma unroll
        for (int nc = 0; nc < 8; nc++)
#pragma unroll
            for (int v = 0; v < 4; v++) d[mc][nc][v] = 0.f;

    float4 pa0, pa1, pw0, pw1;
    pa0 = *(const float4*)&Ap[(size_t)(bm0 + r0) * K + c4];
    pa1 = *(const float4*)&Ap[(size_t)(bm0 + r1) * K + c4];
    pw0 = *(const float4*)&W [(size_t)(bn0 + r0) * K + c4];
    pw1 = *(const float4*)&W [(size_t)(bn0 + r1) * K + c4];
    {
        float4 t;
        t = make_float4(f2tf32f(pa0.x), f2tf32f(pa0.y), f2tf32f(pa0.z), f2tf32f(pa0.w));
        *(float4*)&As[0][r0][c4] = t;
        t = make_float4(f2tf32f(pa1.x), f2tf32f(pa1.y), f2tf32f(pa1.z), f2tf32f(pa1.w));
        *(float4*)&As[0][r1][c4] = t;
        t = make_float4(f2tf32f(pw0.x), f2tf32f(pw0.y), f2tf32f(pw0.z), f2tf32f(pw0.w));
        *(float4*)&Ws[0][r0][c4] = t;
        t = make_float4(f2tf32f(pw1.x), f2tf32f(pw1.y), f2tf32f(pw1.z), f2tf32f(pw1.w));
        *(float4*)&Ws[0][r1][c4] = t;
    }
    __syncthreads();

    int buf = 0;
    for (int k0 = BK; k0 <= K; k0 += BK) {
        const bool more = (k0 < K);
        if (more) {
            pa0 = *(const float4*)&Ap[(size_t)(bm0 + r0) * K + k0 + c4];
            pa1 = *(const float4*)&Ap[(size_t)(bm0 + r1) * K + k0 + c4];
            pw0 = *(const float4*)&W [(size_t)(bn0 + r0) * K + k0 + c4];
            pw1 = *(const float4*)&W [(size_t)(bn0 + r1) * K + k0 + c4];
        }
#pragma unroll
        for (int kk = 0; kk < BK; kk += 8) {
            uint32_t a[2][4];
#pragma unroll
            for (int mc = 0; mc < 2; mc++) {
                int row = wm + mc * 16 + g;
                a[mc][0] = __float_as_uint(As[buf][row    ][kk + tig]);
                a[mc][1] = __float_as_uint(As[buf][row + 8][kk + tig]);
                a[mc][2] = __float_as_uint(As[buf][row    ][kk + tig + 4]);
                a[mc][3] = __float_as_uint(As[buf][row + 8][kk + tig + 4]);
            }
#pragma unroll
            for (int nc = 0; nc < 8; nc++) {
                uint32_t b[2];
                int row = wn + nc * 8 + g;
                b[0] = __float_as_uint(Ws[buf][row][kk + tig]);
                b[1] = __float_as_uint(Ws[buf][row][kk + tig + 4]);
                mma_tf32(d[0][nc], a[0], b);
                mma_tf32(d[1][nc], a[1], b);
            }
        }
        if (more) {
            const int nb = buf ^ 1;
            float4 t;
            t = make_float4(f2tf32f(pa0.x), f2tf32f(pa0.y), f2tf32f(pa0.z), f2tf32f(pa0.w));
            *(float4*)&As[nb][r0][c4] = t;
            t = make_float4(f2tf32f(pa1.x), f2tf32f(pa1.y), f2tf32f(pa1.z), f2tf32f(pa1.w));
            *(float4*)&As[nb][r1][c4] = t;
            t = make_float4(f2tf32f(pw0.x), f2tf32f(pw0.y), f2tf32f(pw0.z), f2tf32f(pw0.w));
            *(float4*)&Ws[nb][r0][c4] = t;
            t = make_float4(f2tf32f(pw1.x), f2tf32f(pw1.y), f2tf32f(pw1.z), f2tf32f(pw1.w));
            *(float4*)&Ws[nb][r1][c4] = t;
            __syncthreads();
            buf = nb;
        }
    }

    // Epilogue: fragment layout rows {g, g+8}, cols {2*tig, 2*tig+1}
#pragma unroll
    for (int mc = 0; mc < 2; mc++) {
#pragma unroll
        for (int nc = 0; nc < 8; nc++) {
            int n = bn0 + wn + nc * 8 + tig * 2;
#pragma unroll
            for (int rr = 0; rr < 2; rr++) {
                int m = bm0 + wm + mc * 16 + g + rr * 8;
                float2 val = make_float2(d[mc][nc][rr * 2 + 0], d[mc][nc][rr * 2 + 1]);
                if (SCATTER) {
                    int bb = m >> 11;
                    int tt = m & 2047;
                    int hh = n >> 6;
                    int dd = n & 63;
                    *(float2*)&dst[(((size_t)bb * NH + hh) * TLEN + tt) * DH + dd] = val;
                } else {
                    *(float2*)&dst[(size_t)m * CDIM + n] = val;
                }
            }
        }
    }
}

// ----------------------------------------------------------------------------
// Causal flash attention, register-tiled (unchanged, fp32 exact).
// ----------------------------------------------------------------------------
#define ALD 65
__global__ void __launch_bounds__(256, 3) attn_kernel()
{
    extern __shared__ float sm[];
    float* qs = sm;
    float* ks = sm + 64 * ALD;
    float* vs = sm + 2 * 64 * ALD;
    float* ps = sm + 3 * 64 * ALD;

    const int qt = blockIdx.x;
    const int bh = blockIdx.y;
    const float* qg = g_q + (size_t)bh * TLEN * DH;
    const float* kg = g_k + (size_t)bh * TLEN * DH;
    const float* vg = g_v + (size_t)bh * TLEN * DH;

    const int tid = threadIdx.x;
    const int ry  = tid >> 4;
    const int cx  = tid & 15;

#pragma unroll
    for (int l = 0; l < 4; l++) {
        int idx = tid + l * 256;
        int r   = idx >> 4;
        int c4  = (idx & 15) * 4;
        float4 v = *(const float4*)&qg[(size_t)(qt * 64 + r) * DH + c4];
        qs[r * ALD + c4 + 0] = v.x * 0.125f;
        qs[r * ALD + c4 + 1] = v.y * 0.125f;
        qs[r * ALD + c4 + 2] = v.z * 0.125f;
        qs[r * ALD + c4 + 3] = v.w * 0.125f;
    }

    float m[4], lsum[4], o[4][4];
#pragma unroll
    for (int i = 0; i < 4; i++) { m[i] = -INFINITY; lsum[i] = 0.f; }
#pragma unroll
    for (int i = 0; i < 4; i++)
#pragma unroll
        for (int j = 0; j < 4; j++) o[i][j] = 0.f;

    for (int kt = 0; kt <= qt; kt++) {
#pragma unroll
        for (int l = 0; l < 4; l++) {
            int idx = tid + l * 256;
            int r   = idx >> 4;
            int c4  = (idx & 15) * 4;
            float4 kv = *(const float4*)&kg[(size_t)(kt * 64 + r) * DH + c4];
            ks[r * ALD + c4 + 0] = kv.x; ks[r * ALD + c4 + 1] = kv.y;
            ks[r * ALD + c4 + 2] = kv.z; ks[r * ALD + c4 + 3] = kv.w;
            float4 vv = *(const float4*)&vg[(size_t)(kt * 64 + r) * DH + c4];
            vs[r * ALD + c4 + 0] = vv.x; vs[r * ALD + c4 + 1] = vv.y;
            vs[r * ALD + c4 + 2] = vv.z; vs[r * ALD + c4 + 3] = vv.w;
        }
        __syncthreads();

        float s[4][4];
#pragma unroll
        for (int i = 0; i < 4; i++)
#pragma unroll
            for (int j = 0; j < 4; j++) s[i][j] = 0.f;
#pragma unroll 16
        for (int dd = 0; dd < 64; dd++) {
            float a[4], b[4];
#pragma unroll
            for (int i = 0; i < 4; i++) a[i] = qs[(ry * 4 + i) * ALD + dd];
#pragma unroll
            for (int j = 0; j < 4; j++) b[j] = ks[(cx * 4 + j) * ALD + dd];
#pragma unroll
            for (int i = 0; i < 4; i++)
#pragma unroll
                for (int j = 0; j < 4; j++) s[i][j] += a[i] * b[j];
        }

        if (kt == qt) {
#pragma unroll
            for (int i = 0; i < 4; i++)
#pragma unroll
                for (int j = 0; j < 4; j++)
                    if (cx * 4 + j > ry * 4 + i) s[i][j] = -INFINITY;
        }

        float mx[4];
#pragma unroll
        for (int i = 0; i < 4; i++)
            mx[i] = fmaxf(fmaxf(s[i][0], s[i][1]), fmaxf(s[i][2], s[i][3]));
#pragma unroll
        for (int off = 1; off < 16; off <<= 1)
#pragma unroll
            for (int i = 0; i < 4; i++)
                mx[i] = fmaxf(mx[i], __shfl_xor_sync(0xffffffffu, mx[i], off));

        float scale[4];
#pragma unroll
        for (int i = 0; i < 4; i++) {
            float mnew = fmaxf(m[i], mx[i]);
            scale[i] = __expf(m[i] - mnew);
            m[i] = mnew;
        }

        float rs[4] = {0.f, 0.f, 0.f, 0.f};
#pragma unroll
        for (int i = 0; i < 4; i++) {
#pragma unroll
            for (int j = 0; j < 4; j++) {
                float p = __expf(s[i][j] - m[i]);
                ps[(ry * 4 + i) * ALD + cx * 4 + j] = p;
                rs[i] += p;
            }
        }
#pragma unroll
        for (int off = 1; off < 16; off <<= 1)
#pragma unroll
            for (int i = 0; i < 4; i++)
                rs[i] += __shfl_xor_sync(0xffffffffu, rs[i], off);
#pragma unroll
        for (int i = 0; i < 4; i++) {
            lsum[i] = lsum[i] * scale[i] + rs[i];
#pragma unroll
            for (int j = 0; j < 4; j++) o[i][j] *= scale[i];
        }
        __syncthreads();

#pragma unroll 8
        for (int j = 0; j < 64; j++) {
            float a[4], b[4];
#pragma unroll
            for (int i = 0; i < 4; i++) a[i] = ps[(ry * 4 + i) * ALD + j];
#pragma unroll
            for (int jj = 0; jj < 4; jj++) b[jj] = vs[j * ALD + cx * 4 + jj];
#pragma unroll
            for (int i = 0; i < 4; i++)
#pragma unroll
                for (int jj = 0; jj < 4; jj++) o[i][jj] += a[i] * b[jj];
        }
        __syncthreads();
    }

    const int b = bh >> 4;
    const int h = bh & 15;
#pragma unroll
    for (int i = 0; i < 4; i++) {
        float inv = 1.f / lsum[i];
        int t = qt * 64 + ry * 4 + i;
        float4 val = make_float4(o[i][0] * inv, o[i][1] * inv,
                                 o[i][2] * inv, o[i][3] * inv);
        *(float4*)&g_att[((size_t)b * TLEN + t) * CDIM + h * DH + cx * 4] = val;
    }
}

// ----------------------------------------------------------------------------
extern "C" void kernel_launch(void* const* d_in, const int* in_sizes, int n_in,
                              void* d_out, int out_size)
{
    const float* x  = (const float*)d_in[0];
    const float* Wq = (const float*)d_in[1];
    const float* Wk = (const float*)d_in[2];
    const float* Wv = (const float*)d_in[3];
    const float* Wo = (const float*)d_in[4];
    float* out = (float*)d_out;

    gemm_mma_kernel<1><<<dim3(CDIM / 128, MROWS / 128, 3), 256>>>(
        x, Wq, Wk, Wv, nullptr);

    const int smem = 4 * 64 * ALD * sizeof(float);
    cudaFuncSetAttribute(attn_kernel,
                         cudaFuncAttributeMaxDynamicSharedMemorySize, smem);
    attn_kernel<<<dim3(TLEN / 64, BDIM * NH), 256, smem>>>();

    gemm_mma_kernel<0><<<dim3(CDIM / 128, MROWS / 128, 1), 256>>>(
        nullptr, Wo, nullptr, nullptr, out);
}

// round 6
// speedup vs baseline: 5.4221x; 1.8980x over previous
#include <cuda_runtime.h>
#include <cstdint>
#include <math.h>

#define BDIM 2
#define TLEN 2048
#define CDIM 1024
#define NH   16
#define DH   64
#define MROWS (BDIM * TLEN)   // 4096

// Scratch (allocation-free rule: __device__ globals)
__device__ float g_q[(size_t)BDIM * NH * TLEN * DH];
__device__ float g_k[(size_t)BDIM * NH * TLEN * DH];
__device__ float g_v[(size_t)BDIM * NH * TLEN * DH];
__device__ float g_att[(size_t)MROWS * CDIM];   // [B,T,C] layout

// ============================================================================
// helpers
// ============================================================================
__device__ __forceinline__ float f2tf32f(float f) {
    uint32_t r;
    asm("cvt.rna.tf32.f32 %0, %1;" : "=r"(r) : "f"(f));
    return __uint_as_float(r);
}
__device__ __forceinline__ void mma_tf32(float* d, const uint32_t* a,
                                         const uint32_t* b) {
    asm volatile(
        "mma.sync.aligned.m16n8k8.row.col.f32.tf32.tf32.f32 "
        "{%0,%1,%2,%3}, {%4,%5,%6,%7}, {%8,%9}, {%0,%1,%2,%3};"
        : "+f"(d[0]), "+f"(d[1]), "+f"(d[2]), "+f"(d[3])
        : "r"(a[0]), "r"(a[1]), "r"(a[2]), "r"(a[3]), "r"(b[0]), "r"(b[1]));
}

// ============================================================================
// tf32 mma.sync GEMM (unchanged from round 4)
// ============================================================================
#define BK  16
#define LDT 20
template <int SCATTER>
__global__ void __launch_bounds__(256, 2) gemm_mma_kernel(
    const float* __restrict__ A,
    const float* __restrict__ W0,
    const float* __restrict__ W1,
    const float* __restrict__ W2,
    float* __restrict__ Cout)
{
    const int K = CDIM;
    __shared__ float As[2][128][LDT];
    __shared__ float Ws[2][128][LDT];

    const float* W;
    float* dst;
    if (SCATTER) {
        int z = blockIdx.z;
        W   = (z == 0) ? W0  : (z == 1) ? W1  : W2;
        dst = (z == 0) ? g_q : (z == 1) ? g_k : g_v;
    } else {
        W   = W0;
        dst = Cout;
    }
    const float* Ap = SCATTER ? A : g_att;

    const int bm0  = blockIdx.y * 128;
    const int bn0  = blockIdx.x * 128;
    const int tid  = threadIdx.x;
    const int lane = tid & 31;
    const int wid  = tid >> 5;
    const int g    = lane >> 2;
    const int tig  = lane & 3;
    const int wm   = (wid & 3) * 32;
    const int wn   = (wid >> 2) * 64;

    const int r0 = tid >> 2;
    const int c4 = (tid & 3) * 4;
    const int r1 = r0 + 64;

    float d[2][8][4];
#pragma unroll
    for (int mc = 0; mc < 2; mc++)
#pragma unroll
        for (int nc = 0; nc < 8; nc++)
#pragma unroll
            for (int v = 0; v < 4; v++) d[mc][nc][v] = 0.f;

    float4 pa0, pa1, pw0, pw1;
    pa0 = *(const float4*)&Ap[(size_t)(bm0 + r0) * K + c4];
    pa1 = *(const float4*)&Ap[(size_t)(bm0 + r1) * K + c4];
    pw0 = *(const float4*)&W [(size_t)(bn0 + r0) * K + c4];
    pw1 = *(const float4*)&W [(size_t)(bn0 + r1) * K + c4];
    {
        float4 t;
        t = make_float4(f2tf32f(pa0.x), f2tf32f(pa0.y), f2tf32f(pa0.z), f2tf32f(pa0.w));
        *(float4*)&As[0][r0][c4] = t;
        t = make_float4(f2tf32f(pa1.x), f2tf32f(pa1.y), f2tf32f(pa1.z), f2tf32f(pa1.w));
        *(float4*)&As[0][r1][c4] = t;
        t = make_float4(f2tf32f(pw0.x), f2tf32f(pw0.y), f2tf32f(pw0.z), f2tf32f(pw0.w));
        *(float4*)&Ws[0][r0][c4] = t;
        t = make_float4(f2tf32f(pw1.x), f2tf32f(pw1.y), f2tf32f(pw1.z), f2tf32f(pw1.w));
        *(float4*)&Ws[0][r1][c4] = t;
    }
    __syncthreads();

    int buf = 0;
    for (int k0 = BK; k0 <= K; k0 += BK) {
        const bool more = (k0 < K);
        if (more) {
            pa0 = *(const float4*)&Ap[(size_t)(bm0 + r0) * K + k0 + c4];
            pa1 = *(const float4*)&Ap[(size_t)(bm0 + r1) * K + k0 + c4];
            pw0 = *(const float4*)&W [(size_t)(bn0 + r0) * K + k0 + c4];
            pw1 = *(const float4*)&W [(size_t)(bn0 + r1) * K + k0 + c4];
        }
#pragma unroll
        for (int kk = 0; kk < BK; kk += 8) {
            uint32_t a[2][4];
#pragma unroll
            for (int mc = 0; mc < 2; mc++) {
                int row = wm + mc * 16 + g;
                a[mc][0] = __float_as_uint(As[buf][row    ][kk + tig]);
                a[mc][1] = __float_as_uint(As[buf][row + 8][kk + tig]);
                a[mc][2] = __float_as_uint(As[buf][row    ][kk + tig + 4]);
                a[mc][3] = __float_as_uint(As[buf][row + 8][kk + tig + 4]);
            }
#pragma unroll
            for (int nc = 0; nc < 8; nc++) {
                uint32_t b[2];
                int row = wn + nc * 8 + g;
                b[0] = __float_as_uint(Ws[buf][row][kk + tig]);
                b[1] = __float_as_uint(Ws[buf][row][kk + tig + 4]);
                mma_tf32(d[0][nc], a[0], b);
                mma_tf32(d[1][nc], a[1], b);
            }
        }
        if (more) {
            const int nb = buf ^ 1;
            float4 t;
            t = make_float4(f2tf32f(pa0.x), f2tf32f(pa0.y), f2tf32f(pa0.z), f2tf32f(pa0.w));
            *(float4*)&As[nb][r0][c4] = t;
            t = make_float4(f2tf32f(pa1.x), f2tf32f(pa1.y), f2tf32f(pa1.z), f2tf32f(pa1.w));
            *(float4*)&As[nb][r1][c4] = t;
            t = make_float4(f2tf32f(pw0.x), f2tf32f(pw0.y), f2tf32f(pw0.z), f2tf32f(pw0.w));
            *(float4*)&Ws[nb][r0][c4] = t;
            t = make_float4(f2tf32f(pw1.x), f2tf32f(pw1.y), f2tf32f(pw1.z), f2tf32f(pw1.w));
            *(float4*)&Ws[nb][r1][c4] = t;
            __syncthreads();
            buf = nb;
        }
    }

#pragma unroll
    for (int mc = 0; mc < 2; mc++) {
#pragma unroll
        for (int nc = 0; nc < 8; nc++) {
            int n = bn0 + wn + nc * 8 + tig * 2;
#pragma unroll
            for (int rr = 0; rr < 2; rr++) {
                int m = bm0 + wm + mc * 16 + g + rr * 8;
                float2 val = make_float2(d[mc][nc][rr * 2 + 0], d[mc][nc][rr * 2 + 1]);
                if (SCATTER) {
                    int bb = m >> 11;
                    int tt = m & 2047;
                    int hh = n >> 6;
                    int dd = n & 63;
                    *(float2*)&dst[(((size_t)bb * NH + hh) * TLEN + tt) * DH + dd] = val;
                } else {
                    *(float2*)&dst[(size_t)m * CDIM + n] = val;
                }
            }
        }
    }
}

// ============================================================================
// tf32 mma.sync causal flash attention.
// CTA = 128 q rows, 8 warps x 16 rows each (warp-local softmax stats).
// grid = (T/128, B*H), big q-tiles launched first.
// K: [key][d] pad 68; V: [key][d] pad 72; P: warp-private [16][68].
// FIX vs round 5: Q staging loop covers all 128 rows (8 float4s per thread).
// ============================================================================
#define LDQ 68
#define LDK 68
#define LDV 72
#define LDP 68
#define QROWS 128
// smem floats: qs 128*68 + ks 64*68 + vs 64*72 + ps 8*16*68 = 26368
#define ATT_SMEM (26368 * 4)

__global__ void __launch_bounds__(256, 2) attn_mma_kernel()
{
    extern __shared__ float sm[];
    float* qs = sm;                         // [128][LDQ]
    float* ks = qs + QROWS * LDQ;           // [64][LDK]
    float* vs = ks + 64 * LDK;              // [64][LDV]
    float* psa = vs + 64 * LDV;             // [8][16][LDP]

    const int qt = (gridDim.x - 1) - blockIdx.x;   // reversed: big tiles first
    const int bh = blockIdx.y;
    const float* qg = g_q + (size_t)bh * TLEN * DH;
    const float* kg = g_k + (size_t)bh * TLEN * DH;
    const float* vg = g_v + (size_t)bh * TLEN * DH;

    const int tid  = threadIdx.x;
    const int lane = tid & 31;
    const int wid  = tid >> 5;
    const int g    = lane >> 2;
    const int tig  = lane & 3;
    float* ps = psa + wid * 16 * LDP;

    // stage Q tile (scaled by 1/sqrt(Dh), tf32): 128 rows x 16 float4 = 2048
#pragma unroll
    for (int l = 0; l < 8; l++) {
        int idx = tid + l * 256;        // 0..2047
        int r   = idx >> 4;             // 0..127
        int c4  = (idx & 15) * 4;
        float4 v = *(const float4*)&qg[(size_t)(qt * QROWS + r) * DH + c4];
        float4 t = make_float4(f2tf32f(v.x * 0.125f), f2tf32f(v.y * 0.125f),
                               f2tf32f(v.z * 0.125f), f2tf32f(v.w * 0.125f));
        *(float4*)&qs[r * LDQ + c4] = t;
    }

    const int wrow = qt * QROWS + wid * 16;   // warp's first global q row
    float mrow0 = -INFINITY, mrow1 = -INFINITY;
    float lrow0 = 0.f, lrow1 = 0.f;
    float o[8][4];
#pragma unroll
    for (int nc = 0; nc < 8; nc++)
#pragma unroll
        for (int v = 0; v < 4; v++) o[nc][v] = 0.f;

    __syncthreads();   // qs ready

    const int ktmax = 2 * qt + 1;
    for (int kt = 0; kt <= ktmax; kt++) {
        // cooperative K/V tile load (tf32): 64 rows x 16 float4 = 1024
#pragma unroll
        for (int l = 0; l < 4; l++) {
            int idx = tid + l * 256;
            int r   = idx >> 4;
            int c4  = (idx & 15) * 4;
            float4 kv = *(const float4*)&kg[(size_t)(kt * 64 + r) * DH + c4];
            float4 t1 = make_float4(f2tf32f(kv.x), f2tf32f(kv.y),
                                    f2tf32f(kv.z), f2tf32f(kv.w));
            *(float4*)&ks[r * LDK + c4] = t1;
            float4 vv = *(const float4*)&vg[(size_t)(kt * 64 + r) * DH + c4];
            float4 t2 = make_float4(f2tf32f(vv.x), f2tf32f(vv.y),
                                    f2tf32f(vv.z), f2tf32f(vv.w));
            *(float4*)&vs[r * LDV + c4] = t2;
        }
        __syncthreads();

        if (kt * 64 <= wrow + 15) {   // warp has unmasked work in this tile
            // ---- S = Q K^T ----
            float s[8][4];
#pragma unroll
            for (int nc = 0; nc < 8; nc++)
#pragma unroll
                for (int v = 0; v < 4; v++) s[nc][v] = 0.f;
#pragma unroll
            for (int kk8 = 0; kk8 < 8; kk8++) {
                const int kk = kk8 * 8;
                uint32_t a[4];
                a[0] = __float_as_uint(qs[(wid * 16 + g    ) * LDQ + kk + tig]);
                a[1] = __float_as_uint(qs[(wid * 16 + g + 8) * LDQ + kk + tig]);
                a[2] = __float_as_uint(qs[(wid * 16 + g    ) * LDQ + kk + tig + 4]);
                a[3] = __float_as_uint(qs[(wid * 16 + g + 8) * LDQ + kk + tig + 4]);
#pragma unroll
                for (int nc = 0; nc < 8; nc++) {
                    uint32_t b[2];
                    b[0] = __float_as_uint(ks[(nc * 8 + g) * LDK + kk + tig]);
                    b[1] = __float_as_uint(ks[(nc * 8 + g) * LDK + kk + tig + 4]);
                    mma_tf32(s[nc], a, b);
                }
            }

            // ---- causal mask (boundary tiles) ----
            if (kt * 64 + 63 > wrow) {
#pragma unroll
                for (int nc = 0; nc < 8; nc++) {
                    int col = kt * 64 + nc * 8 + 2 * tig;
                    if (col     > wrow + g)     s[nc][0] = -INFINITY;
                    if (col + 1 > wrow + g)     s[nc][1] = -INFINITY;
                    if (col     > wrow + g + 8) s[nc][2] = -INFINITY;
                    if (col + 1 > wrow + g + 8) s[nc][3] = -INFINITY;
                }
            }

            // ---- warp-local online softmax ----
            float t0 = -INFINITY, t1 = -INFINITY;
#pragma unroll
            for (int nc = 0; nc < 8; nc++) {
                t0 = fmaxf(t0, fmaxf(s[nc][0], s[nc][1]));
                t1 = fmaxf(t1, fmaxf(s[nc][2], s[nc][3]));
            }
            t0 = fmaxf(t0, __shfl_xor_sync(0xffffffffu, t0, 1));
            t0 = fmaxf(t0, __shfl_xor_sync(0xffffffffu, t0, 2));
            t1 = fmaxf(t1, __shfl_xor_sync(0xffffffffu, t1, 1));
            t1 = fmaxf(t1, __shfl_xor_sync(0xffffffffu, t1, 2));
            float mn0 = fmaxf(mrow0, t0);
            float mn1 = fmaxf(mrow1, t1);
            float sc0 = __expf(mrow0 - mn0);
            float sc1 = __expf(mrow1 - mn1);
            mrow0 = mn0; mrow1 = mn1;

            float rs0 = 0.f, rs1 = 0.f;
#pragma unroll
            for (int nc = 0; nc < 8; nc++) {
                float p0 = f2tf32f(__expf(s[nc][0] - mn0));
                float p1 = f2tf32f(__expf(s[nc][1] - mn0));
                float p2 = f2tf32f(__expf(s[nc][2] - mn1));
                float p3 = f2tf32f(__expf(s[nc][3] - mn1));
                rs0 += p0 + p1;
                rs1 += p2 + p3;
                *(float2*)&ps[(g    ) * LDP + nc * 8 + 2 * tig] = make_float2(p0, p1);
                *(float2*)&ps[(g + 8) * LDP + nc * 8 + 2 * tig] = make_float2(p2, p3);
            }
            rs0 += __shfl_xor_sync(0xffffffffu, rs0, 1);
            rs0 += __shfl_xor_sync(0xffffffffu, rs0, 2);
            rs1 += __shfl_xor_sync(0xffffffffu, rs1, 1);
            rs1 += __shfl_xor_sync(0xffffffffu, rs1, 2);
            lrow0 = lrow0 * sc0 + rs0;
            lrow1 = lrow1 * sc1 + rs1;
#pragma unroll
            for (int nc = 0; nc < 8; nc++) {
                o[nc][0] *= sc0; o[nc][1] *= sc0;
                o[nc][2] *= sc1; o[nc][3] *= sc1;
            }
            __syncwarp();

            // ---- O += P V ----
#pragma unroll
            for (int kk8 = 0; kk8 < 8; kk8++) {
                const int kk = kk8 * 8;
                uint32_t a[4];
                a[0] = __float_as_uint(ps[(g    ) * LDP + kk + tig]);
                a[1] = __float_as_uint(ps[(g + 8) * LDP + kk + tig]);
                a[2] = __float_as_uint(ps[(g    ) * LDP + kk + tig + 4]);
                a[3] = __float_as_uint(ps[(g + 8) * LDP + kk + tig + 4]);
#pragma unroll
                for (int nc = 0; nc < 8; nc++) {
                    uint32_t b[2];
                    b[0] = __float_as_uint(vs[(kk + tig    ) * LDV + nc * 8 + g]);
                    b[1] = __float_as_uint(vs[(kk + tig + 4) * LDV + nc * 8 + g]);
                    mma_tf32(o[nc], a, b);
                }
            }
        }
        __syncthreads();   // protect ks/vs for next tile
    }

    // ---- normalize & write to g_att [B,T,C] ----
    const int b = bh >> 4;
    const int h = bh & 15;
    const float inv0 = 1.f / lrow0;
    const float inv1 = 1.f / lrow1;
    const int t0r = wrow + g;
    const int t1r = wrow + g + 8;
#pragma unroll
    for (int nc = 0; nc < 8; nc++) {
        int d = h * DH + nc * 8 + 2 * tig;
        *(float2*)&g_att[((size_t)b * TLEN + t0r) * CDIM + d] =
            make_float2(o[nc][0] * inv0, o[nc][1] * inv0);
        *(float2*)&g_att[((size_t)b * TLEN + t1r) * CDIM + d] =
            make_float2(o[nc][2] * inv1, o[nc][3] * inv1);
    }
}

// ----------------------------------------------------------------------------
extern "C" void kernel_launch(void* const* d_in, const int* in_sizes, int n_in,
                              void* d_out, int out_size)
{
    const float* x  = (const float*)d_in[0];
    const float* Wq = (const float*)d_in[1];
    const float* Wk = (const float*)d_in[2];
    const float* Wv = (const float*)d_in[3];
    const float* Wo = (const float*)d_in[4];
    float* out = (float*)d_out;

    gemm_mma_kernel<1><<<dim3(CDIM / 128, MROWS / 128, 3), 256>>>(
        x, Wq, Wk, Wv, nullptr);

    cudaFuncSetAttribute(attn_mma_kernel,
                         cudaFuncAttributeMaxDynamicSharedMemorySize, ATT_SMEM);
    attn_mma_kernel<<<dim3(TLEN / QROWS, BDIM * NH), 256, ATT_SMEM>>>();

    gemm_mma_kernel<0><<<dim3(CDIM / 128, MROWS / 128, 1), 256>>>(
        nullptr, Wo, nullptr, nullptr, out);
}